// round 2
// baseline (speedup 1.0000x reference)
#include <cuda_runtime.h>
#include <math.h>
#include <stdint.h>

#define Bn    4
#define COH   128
#define COW   128
#define CLS   19
#define FIH   256
#define FIW   256
#define FIC   256
#define PTR   8192
#define POS   24576
#define NUNC  6144
#define NRAND 2048
#define NSORT 32768
#define KDIM  275
#define KPAD  288
#define NH    256
#define CHUNK 4096

// ------------------------- scratch (device globals, no allocs) -------------
__device__ unsigned long long g_keys[Bn * NSORT];
__device__ float g_Ha[(size_t)Bn * PTR * KPAD];
__device__ float g_Hb[(size_t)Bn * PTR * KPAD];

// ------------------------- f32x2 helpers -----------------------------------
__device__ __forceinline__ unsigned long long pack2(float x, float y) {
    unsigned long long r;
    asm("mov.b64 %0, {%1,%2};" : "=l"(r) : "f"(x), "f"(y));
    return r;
}
__device__ __forceinline__ void unpack2(unsigned long long v, float& lo, float& hi) {
    asm("mov.b64 {%0,%1}, %2;" : "=f"(lo), "=f"(hi) : "l"(v));
}
__device__ __forceinline__ void ffma2(unsigned long long& acc, unsigned long long a,
                                      unsigned long long b) {
    asm("fma.rn.f32x2 %0, %1, %2, %0;" : "+l"(acc) : "l"(a), "l"(b));
}

// strict (non-contracted) lerp: (1-w)*a + w*b with rn at every step
__device__ __forceinline__ float lerp_rn(float w, float a, float b) {
    return __fadd_rn(__fmul_rn(__fsub_rn(1.0f, w), a), __fmul_rn(w, b));
}

// ------------------------- 1. uncertainty (bit-exact path) ------------------
__global__ void k_uncertainty(const float* __restrict__ coarse, const float* __restrict__ rc) {
    int t = blockIdx.x * 256 + threadIdx.x;   // 0 .. 4*32768-1
    int b = t >> 15;
    int p = t & (NSORT - 1);
    if (p >= POS) { g_keys[t] = ~0ull; return; }
    float cy = rc[((size_t)b * POS + p) * 2 + 0];
    float cx = rc[((size_t)b * POS + p) * 2 + 1];
    // *128 is exact (power of 2); -0.5 rn
    float y = __fadd_rn(__fmul_rn(cy, 128.f), -0.5f);
    float x = __fadd_rn(__fmul_rn(cx, 128.f), -0.5f);
    float y0f = floorf(y), x0f = floorf(x);
    float wy = __fsub_rn(y, y0f);   // exact
    float wx = __fsub_rn(x, x0f);   // exact
    int y0 = min(max((int)y0f, 0), COH - 1);
    int y1 = min(max((int)y0f + 1, 0), COH - 1);
    int x0 = min(max((int)x0f, 0), COW - 1);
    int x1 = min(max((int)x0f + 1, 0), COW - 1);
    const float* cb = coarse + (size_t)b * COH * COW * CLS;
    const float* p00 = cb + (y0 * COW + x0) * CLS;
    const float* p01 = cb + (y0 * COW + x1) * CLS;
    const float* p10 = cb + (y1 * COW + x0) * CLS;
    const float* p11 = cb + (y1 * COW + x1) * CLS;
    float m1 = -3.0e38f, m2 = -3.0e38f;
#pragma unroll
    for (int c = 0; c < CLS; c++) {
        float top = lerp_rn(wx, p00[c], p01[c]);
        float bot = lerp_rn(wx, p10[c], p11[c]);
        float v = lerp_rn(wy, top, bot);
        if (v > m1) { m2 = m1; m1 = v; }
        else if (v > m2) m2 = v;
    }
    float unc = __fsub_rn(m2, m1);
    unsigned u = __float_as_uint(unc);
    u = (u & 0x80000000u) ? ~u : (u | 0x80000000u);  // ascending order int
    u = ~u;                                          // descending by value
    g_keys[t] = ((unsigned long long)u << 32) | (unsigned)p;
}

// ------------------------- 2. bitonic sort ---------------------------------
__global__ void k_lsort() {
    __shared__ unsigned long long s[CHUNK];
    int base = blockIdx.x * CHUNK;
    int lbase = base & (NSORT - 1);
    for (int i = threadIdx.x; i < CHUNK; i += 256) s[i] = g_keys[base + i];
    __syncthreads();
    for (int k = 2; k <= CHUNK; k <<= 1) {
        for (int j = k >> 1; j > 0; j >>= 1) {
            for (int t = threadIdx.x; t < CHUNK / 2; t += 256) {
                int i = ((t & ~(j - 1)) << 1) | (t & (j - 1));
                int ixj = i + j;
                bool up = (((lbase + i) & k) == 0);
                unsigned long long A = s[i], Bv = s[ixj];
                if ((A > Bv) == up) { s[i] = Bv; s[ixj] = A; }
            }
            __syncthreads();
        }
    }
    for (int i = threadIdx.x; i < CHUNK; i += 256) g_keys[base + i] = s[i];
}

__global__ void k_gmerge(int j, int k) {
    int t = blockIdx.x * 256 + threadIdx.x;  // 65536 pairs
    int b = t >> 14, tl = t & 16383;
    int i = ((tl & ~(j - 1)) << 1) | (tl & (j - 1));
    bool up = ((i & k) == 0);
    size_t gi = (size_t)b * NSORT + i;
    unsigned long long A = g_keys[gi], Bv = g_keys[gi + j];
    if ((A > Bv) == up) { g_keys[gi] = Bv; g_keys[gi + j] = A; }
}

__global__ void k_lmerge(int k) {
    __shared__ unsigned long long s[CHUNK];
    int base = blockIdx.x * CHUNK;
    int lbase = base & (NSORT - 1);
    for (int i = threadIdx.x; i < CHUNK; i += 256) s[i] = g_keys[base + i];
    __syncthreads();
    for (int j = CHUNK >> 1; j > 0; j >>= 1) {
        for (int t = threadIdx.x; t < CHUNK / 2; t += 256) {
            int i = ((t & ~(j - 1)) << 1) | (t & (j - 1));
            int ixj = i + j;
            bool up = (((lbase + i) & k) == 0);
            unsigned long long A = s[i], Bv = s[ixj];
            if ((A > Bv) == up) { s[i] = Bv; s[ixj] = A; }
        }
        __syncthreads();
    }
    for (int i = threadIdx.x; i < CHUNK; i += 256) g_keys[base + i] = s[i];
}

// ------------------------- 3. gather coords --------------------------------
__global__ void k_coords(const float* __restrict__ rc, const float* __restrict__ rf,
                         float* __restrict__ oc) {
    int t = blockIdx.x * 256 + threadIdx.x;  // 0..32767
    int b = t >> 13, p = t & (PTR - 1);
    float y, x;
    if (p < NUNC) {
        unsigned idx = (unsigned)(g_keys[(size_t)b * NSORT + p] & 0xffffffffu);
        y = rc[((size_t)b * POS + idx) * 2 + 0];
        x = rc[((size_t)b * POS + idx) * 2 + 1];
    } else {
        int q = p - NUNC;
        y = rf[((size_t)b * NRAND + q) * 2 + 0];
        x = rf[((size_t)b * NRAND + q) * 2 + 1];
    }
    oc[(size_t)t * 2 + 0] = y;
    oc[(size_t)t * 2 + 1] = x;
}

// ------------------------- 4. feature sampling (warp/point) ----------------
__global__ void k_sample(const float* __restrict__ coarse, const float* __restrict__ fine,
                         const float* __restrict__ oc, float* __restrict__ Ha,
                         float* __restrict__ Hb) {
    int gt = blockIdx.x * 256 + threadIdx.x;
    int w = gt >> 5, lane = gt & 31;
    int b = w >> 13;
    float cy = oc[(size_t)w * 2 + 0], cx = oc[(size_t)w * 2 + 1];
    size_t row = (size_t)w * KPAD;

    {   // coarse -> cols [256..274], zeros -> [275..287]
        float y = cy * 128.f - 0.5f, x = cx * 128.f - 0.5f;
        float y0f = floorf(y), x0f = floorf(x);
        float wy = y - y0f, wx = x - x0f;
        int y0 = min(max((int)y0f, 0), COH - 1);
        int y1 = min(max((int)y0f + 1, 0), COH - 1);
        int x0 = min(max((int)x0f, 0), COW - 1);
        int x1 = min(max((int)x0f + 1, 0), COW - 1);
        const float* cb = coarse + (size_t)b * COH * COW * CLS;
        if (lane < CLS) {
            float a = cb[(y0 * COW + x0) * CLS + lane];
            float b2 = cb[(y0 * COW + x1) * CLS + lane];
            float c = cb[(y1 * COW + x0) * CLS + lane];
            float d = cb[(y1 * COW + x1) * CLS + lane];
            float v = (1.f - wy) * ((1.f - wx) * a + wx * b2) +
                      wy * ((1.f - wx) * c + wx * d);
            Ha[row + 256 + lane] = v;
            Hb[row + 256 + lane] = v;
        } else {
            Ha[row + 256 + lane] = 0.f;  // lanes 19..31 -> cols 275..287
            Hb[row + 256 + lane] = 0.f;
        }
    }
    {   // fine -> cols [0..255]
        float y = cy * 256.f - 0.5f, x = cx * 256.f - 0.5f;
        float y0f = floorf(y), x0f = floorf(x);
        float wy = y - y0f, wx = x - x0f;
        int y0 = min(max((int)y0f, 0), FIH - 1);
        int y1 = min(max((int)y0f + 1, 0), FIH - 1);
        int x0 = min(max((int)x0f, 0), FIW - 1);
        int x1 = min(max((int)x0f + 1, 0), FIW - 1);
        const float* fb = fine + (size_t)b * FIH * FIW * FIC;
        const float4* f00 = (const float4*)(fb + ((size_t)y0 * FIW + x0) * FIC);
        const float4* f01 = (const float4*)(fb + ((size_t)y0 * FIW + x1) * FIC);
        const float4* f10 = (const float4*)(fb + ((size_t)y1 * FIW + x0) * FIC);
        const float4* f11 = (const float4*)(fb + ((size_t)y1 * FIW + x1) * FIC);
#pragma unroll
        for (int q = 0; q < 2; q++) {
            int c4 = lane + 32 * q;
            float4 a = f00[c4], b2 = f01[c4], c = f10[c4], d = f11[c4];
            float4 r;
            r.x = (1.f - wy) * ((1.f - wx) * a.x + wx * b2.x) + wy * ((1.f - wx) * c.x + wx * d.x);
            r.y = (1.f - wy) * ((1.f - wx) * a.y + wx * b2.y) + wy * ((1.f - wx) * c.y + wx * d.y);
            r.z = (1.f - wy) * ((1.f - wx) * a.z + wx * b2.z) + wy * ((1.f - wx) * c.z + wx * d.z);
            r.w = (1.f - wy) * ((1.f - wx) * a.w + wx * b2.w) + wy * ((1.f - wx) * c.w + wx * d.w);
            *(float4*)&Ha[row + (size_t)c4 * 4] = r;
        }
    }
}

// ------------------------- 5. hidden GEMM (relu, f32x2) --------------------
// C[32768,256] = relu(X[32768,275(pad288)] @ W[275,256] + b). perm=1: layer-0
// row permutation (X is [fine|coarse], W rows are [coarse|fine]).
#define BM 64
#define BN 256
#define KC 16
__global__ __launch_bounds__(256) void k_gemm_relu(const float* __restrict__ X,
                                                   const float* __restrict__ W,
                                                   const float* __restrict__ bias,
                                                   float* __restrict__ Y, int perm) {
    __shared__ float As[KC][BM];
    __shared__ float Bs[KC][BN];
    int t = threadIdx.x;
    int tx = t & 31, ty = t >> 5;
    int m0 = blockIdx.x * BM;

    unsigned long long acc[8][4];
#pragma unroll
    for (int i = 0; i < 8; i++)
#pragma unroll
        for (int j = 0; j < 4; j++) acc[i][j] = 0ull;

    int am = t >> 2;         // 0..63
    int ak = (t & 3) * 4;    // 0,4,8,12
    int bk = t >> 4;         // 0..15
    int bc = (t & 15) * 16;  // 0..240

    for (int kc0 = 0; kc0 < KPAD; kc0 += KC) {
        float4 av = *(const float4*)&X[(size_t)(m0 + am) * KPAD + kc0 + ak];
        As[ak + 0][am] = av.x;
        As[ak + 1][am] = av.y;
        As[ak + 2][am] = av.z;
        As[ak + 3][am] = av.w;
        int klog = kc0 + bk;
        int wr = perm ? (klog < 256 ? klog + CLS : (klog < KDIM ? klog - 256 : -1))
                      : (klog < KDIM ? klog : -1);
#pragma unroll
        for (int q = 0; q < 4; q++) {
            float4 bv = (wr >= 0) ? *(const float4*)&W[(size_t)wr * NH + bc + q * 4]
                                  : make_float4(0.f, 0.f, 0.f, 0.f);
            *(float4*)&Bs[bk][bc + q * 4] = bv;
        }
        __syncthreads();
#pragma unroll
        for (int kk = 0; kk < KC; kk++) {
            float4 a0 = *(const float4*)&As[kk][ty * 8];
            float4 a1 = *(const float4*)&As[kk][ty * 8 + 4];
            unsigned long long bp[4];
#pragma unroll
            for (int j = 0; j < 4; j++)
                bp[j] = *(const unsigned long long*)&Bs[kk][tx * 8 + j * 2];
            float aa[8] = {a0.x, a0.y, a0.z, a0.w, a1.x, a1.y, a1.z, a1.w};
#pragma unroll
            for (int i = 0; i < 8; i++) {
                unsigned long long ap = pack2(aa[i], aa[i]);
#pragma unroll
                for (int j = 0; j < 4; j++) ffma2(acc[i][j], ap, bp[j]);
            }
        }
        __syncthreads();
    }
#pragma unroll
    for (int i = 0; i < 8; i++) {
        size_t m = m0 + ty * 8 + i;
        float c[8];
#pragma unroll
        for (int j = 0; j < 4; j++) {
            float lo, hi;
            unpack2(acc[i][j], lo, hi);
            c[2 * j] = lo;
            c[2 * j + 1] = hi;
        }
#pragma unroll
        for (int j = 0; j < 8; j++) {
            float v = c[j] + bias[tx * 8 + j];
            c[j] = v > 0.f ? v : 0.f;
        }
        *(float4*)&Y[m * KPAD + tx * 8] = make_float4(c[0], c[1], c[2], c[3]);
        *(float4*)&Y[m * KPAD + tx * 8 + 4] = make_float4(c[4], c[5], c[6], c[7]);
    }
}

// ------------------------- 6. final layer (N=19) ---------------------------
__global__ __launch_bounds__(256) void k_final(const float* __restrict__ X,
                                               const float* __restrict__ wf,
                                               const float* __restrict__ bf,
                                               float* __restrict__ out) {
    __shared__ float swf[KDIM * CLS];
    for (int i = threadIdx.x; i < KDIM * CLS; i += 256) swf[i] = wf[i];
    __syncthreads();
    int w = (blockIdx.x * 256 + threadIdx.x) >> 5;  // point id
    int lane = threadIdx.x & 31;
    const float* xr = X + (size_t)w * KPAD;
    float acc[CLS];
#pragma unroll
    for (int c = 0; c < CLS; c++) acc[c] = 0.f;
    for (int k = lane; k < KDIM; k += 32) {
        float xv = xr[k];
        const float* wr = &swf[k * CLS];
#pragma unroll
        for (int c = 0; c < CLS; c++) acc[c] += xv * wr[c];
    }
#pragma unroll
    for (int off = 16; off; off >>= 1)
#pragma unroll
        for (int c = 0; c < CLS; c++) acc[c] += __shfl_xor_sync(0xffffffffu, acc[c], off);
    if (lane == 0) {
        float* o = out + (size_t)w * CLS;
#pragma unroll
        for (int c = 0; c < CLS; c++) o[c] = acc[c] + bf[c];
    }
}

// ------------------------- 7. resize + softmax -----------------------------
__global__ void k_resize_softmax(const float* __restrict__ coarse, float* __restrict__ op) {
    int t = blockIdx.x * 256 + threadIdx.x;  // 0 .. 4*512*512-1
    int b = t >> 18;
    int rem = t & 262143;
    int y = rem >> 9;
    int x = rem & 511;
    float sy = (y + 0.5f) * 0.25f - 0.5f;
    float sx = (x + 0.5f) * 0.25f - 0.5f;
    float y0f = floorf(sy), x0f = floorf(sx);
    float wy = sy - y0f, wx = sx - x0f;
    int y0 = min(max((int)y0f, 0), COH - 1);
    int y1 = min(max((int)y0f + 1, 0), COH - 1);
    int x0 = min(max((int)x0f, 0), COW - 1);
    int x1 = min(max((int)x0f + 1, 0), COW - 1);
    const float* cb = coarse + (size_t)b * COH * COW * CLS;
    const float* p00 = cb + (y0 * COW + x0) * CLS;
    const float* p01 = cb + (y0 * COW + x1) * CLS;
    const float* p10 = cb + (y1 * COW + x0) * CLS;
    const float* p11 = cb + (y1 * COW + x1) * CLS;
    float v[CLS];
    float m = -3.0e38f;
#pragma unroll
    for (int c = 0; c < CLS; c++) {
        float top = (1.f - wx) * p00[c] + wx * p01[c];
        float bot = (1.f - wx) * p10[c] + wx * p11[c];
        v[c] = (1.f - wy) * top + wy * bot;
        m = fmaxf(m, v[c]);
    }
    float s = 0.f;
#pragma unroll
    for (int c = 0; c < CLS; c++) {
        v[c] = expf(v[c] - m);
        s += v[c];
    }
    float inv = 1.f / s;
    float* o = op + (size_t)t * CLS;
#pragma unroll
    for (int c = 0; c < CLS; c++) o[c] = v[c] * inv;
}

// ------------------------- launch ------------------------------------------
extern "C" void kernel_launch(void* const* d_in, const int* in_sizes, int n_in, void* d_out,
                              int out_size) {
    const float* coarse = (const float*)d_in[1];
    const float* fine0 = (const float*)d_in[2];
    const float* rand_coords = (const float*)d_in[3];
    const float* rand_fill = (const float*)d_in[4];
    const float* w0 = (const float*)d_in[5];
    const float* b0 = (const float*)d_in[6];
    const float* w1 = (const float*)d_in[7];
    const float* b1 = (const float*)d_in[8];
    const float* w2 = (const float*)d_in[9];
    const float* b2 = (const float*)d_in[10];
    const float* wf = (const float*)d_in[11];
    const float* bf = (const float*)d_in[12];
    float* out = (float*)d_out;

    const size_t PROBS = (size_t)Bn * 512 * 512 * CLS;
    const size_t LOGITS = (size_t)Bn * PTR * CLS;
    float* out_probs = out;
    float* out_logits = out + PROBS;
    float* out_coords = out + PROBS + LOGITS;

    void* pHa = nullptr;
    void* pHb = nullptr;
    cudaGetSymbolAddress(&pHa, g_Ha);
    cudaGetSymbolAddress(&pHb, g_Hb);
    float* Ha = (float*)pHa;
    float* Hb = (float*)pHb;

    // independent big-memory path first
    k_resize_softmax<<<4096, 256>>>(coarse, out_probs);

    // uncertainty + per-batch bitonic sort of 32768 keys
    k_uncertainty<<<512, 256>>>(coarse, rand_coords);
    k_lsort<<<32, 256>>>();
    k_gmerge<<<256, 256>>>(4096, 8192);
    k_lmerge<<<32, 256>>>(8192);
    k_gmerge<<<256, 256>>>(8192, 16384);
    k_gmerge<<<256, 256>>>(4096, 16384);
    k_lmerge<<<32, 256>>>(16384);
    k_gmerge<<<256, 256>>>(16384, 32768);
    k_gmerge<<<256, 256>>>(8192, 32768);
    k_gmerge<<<256, 256>>>(4096, 32768);
    k_lmerge<<<32, 256>>>(32768);

    k_coords<<<128, 256>>>(rand_coords, rand_fill, out_coords);
    k_sample<<<4096, 256>>>(coarse, fine0, out_coords, Ha, Hb);

    k_gemm_relu<<<512, 256>>>(Ha, w0, b0, Hb, 1);
    k_gemm_relu<<<512, 256>>>(Hb, w1, b1, Ha, 0);
    k_gemm_relu<<<512, 256>>>(Ha, w2, b2, Hb, 0);
    k_final<<<4096, 256>>>(Hb, wf, bf, out_logits);
}

// round 4
// speedup vs baseline: 1.5932x; 1.5932x over previous
#include <cuda_runtime.h>
#include <cuda_bf16.h>
#include <math.h>
#include <stdint.h>

#define Bn    4
#define COH   128
#define COW   128
#define CLS   19
#define FIH   256
#define FIW   256
#define FIC   256
#define PTR   8192
#define POS   24576
#define NUNC  6144
#define NRAND 2048
#define NSORT 32768
#define KDIM  275
#define NH    256
#define CHUNK 4096
#define KP2   320        // padded K for tensor path (10 x 32)
#define MTOT  32768      // Bn*PTR

// ------------------------- scratch (device globals, no allocs) -------------
__device__ unsigned long long g_keys[Bn * NSORT];
__device__ __align__(16) __nv_bfloat16 g_Xa_hi[(size_t)MTOT * KP2];
__device__ __align__(16) __nv_bfloat16 g_Xa_lo[(size_t)MTOT * KP2];
__device__ __align__(16) __nv_bfloat16 g_Xb_hi[(size_t)MTOT * KP2];
__device__ __align__(16) __nv_bfloat16 g_Xb_lo[(size_t)MTOT * KP2];
__device__ __align__(16) __nv_bfloat16 g_Wt_hi[3 * 256 * KP2];
__device__ __align__(16) __nv_bfloat16 g_Wt_lo[3 * 256 * KP2];

// ------------------------- small helpers -----------------------------------
__device__ __forceinline__ float lerp_rn(float w, float a, float b) {
    return __fadd_rn(__fmul_rn(__fsub_rn(1.0f, w), a), __fmul_rn(w, b));
}
__device__ __forceinline__ float bf_hi(float v) {
    return __bfloat162float(__float2bfloat16(v));
}
// pack two floats as bf16x2; elem0 (low half) = e0, elem1 (high half) = e1
__device__ __forceinline__ uint32_t packbf(float e0, float e1) {
    uint32_t r;
    asm("cvt.rn.bf16x2.f32 %0, %1, %2;" : "=r"(r) : "f"(e1), "f"(e0));
    return r;
}
__device__ __forceinline__ uint32_t smem_u32(const void* p) {
    uint32_t a;
    asm("{ .reg .u64 t; cvta.to.shared.u64 t, %1; cvt.u32.u64 %0, t; }" : "=r"(a) : "l"(p));
    return a;
}
__device__ __forceinline__ void cp16(uint32_t dst, const void* src) {
    asm volatile("cp.async.cg.shared.global [%0], [%1], 16;" :: "r"(dst), "l"(src) : "memory");
}
__device__ __forceinline__ void cp_commit() {
    asm volatile("cp.async.commit_group;" ::: "memory");
}
template <int N>
__device__ __forceinline__ void cp_wait() {
    asm volatile("cp.async.wait_group %0;" :: "n"(N) : "memory");
}
__device__ __forceinline__ void ldsm4(uint32_t r[4], uint32_t addr) {
    asm volatile("ldmatrix.sync.aligned.m8n8.x4.shared.b16 {%0,%1,%2,%3}, [%4];"
                 : "=r"(r[0]), "=r"(r[1]), "=r"(r[2]), "=r"(r[3]) : "r"(addr));
}
__device__ __forceinline__ void ldsm2(uint32_t r[2], uint32_t addr) {
    asm volatile("ldmatrix.sync.aligned.m8n8.x2.shared.b16 {%0,%1}, [%2];"
                 : "=r"(r[0]), "=r"(r[1]) : "r"(addr));
}
__device__ __forceinline__ void mma_bf16(float c[4], const uint32_t a[4], const uint32_t b[2]) {
    asm volatile(
        "mma.sync.aligned.m16n8k16.row.col.f32.bf16.bf16.f32 "
        "{%0,%1,%2,%3}, {%4,%5,%6,%7}, {%8,%9}, {%0,%1,%2,%3};"
        : "+f"(c[0]), "+f"(c[1]), "+f"(c[2]), "+f"(c[3])
        : "r"(a[0]), "r"(a[1]), "r"(a[2]), "r"(a[3]), "r"(b[0]), "r"(b[1]));
}

// ------------------------- 1. uncertainty (bit-exact path) ------------------
__global__ void k_uncertainty(const float* __restrict__ coarse, const float* __restrict__ rc) {
    int t = blockIdx.x * 256 + threadIdx.x;
    int b = t >> 15;
    int p = t & (NSORT - 1);
    if (p >= POS) { g_keys[t] = ~0ull; return; }
    float cy = rc[((size_t)b * POS + p) * 2 + 0];
    float cx = rc[((size_t)b * POS + p) * 2 + 1];
    float y = __fadd_rn(__fmul_rn(cy, 128.f), -0.5f);
    float x = __fadd_rn(__fmul_rn(cx, 128.f), -0.5f);
    float y0f = floorf(y), x0f = floorf(x);
    float wy = __fsub_rn(y, y0f);
    float wx = __fsub_rn(x, x0f);
    int y0 = min(max((int)y0f, 0), COH - 1);
    int y1 = min(max((int)y0f + 1, 0), COH - 1);
    int x0 = min(max((int)x0f, 0), COW - 1);
    int x1 = min(max((int)x0f + 1, 0), COW - 1);
    const float* cb = coarse + (size_t)b * COH * COW * CLS;
    const float* p00 = cb + (y0 * COW + x0) * CLS;
    const float* p01 = cb + (y0 * COW + x1) * CLS;
    const float* p10 = cb + (y1 * COW + x0) * CLS;
    const float* p11 = cb + (y1 * COW + x1) * CLS;
    float m1 = -3.0e38f, m2 = -3.0e38f;
#pragma unroll
    for (int c = 0; c < CLS; c++) {
        float top = lerp_rn(wx, p00[c], p01[c]);
        float bot = lerp_rn(wx, p10[c], p11[c]);
        float v = lerp_rn(wy, top, bot);
        if (v > m1) { m2 = m1; m1 = v; }
        else if (v > m2) m2 = v;
    }
    float unc = __fsub_rn(m2, m1);
    unsigned u = __float_as_uint(unc);
    u = (u & 0x80000000u) ? ~u : (u | 0x80000000u);
    u = ~u;
    g_keys[t] = ((unsigned long long)u << 32) | (unsigned)p;
}

// ------------------------- 2. bitonic sort ---------------------------------
__global__ void k_lsort() {
    __shared__ unsigned long long s[CHUNK];
    int base = blockIdx.x * CHUNK;
    int lbase = base & (NSORT - 1);
    for (int i = threadIdx.x; i < CHUNK; i += 256) s[i] = g_keys[base + i];
    __syncthreads();
    for (int k = 2; k <= CHUNK; k <<= 1) {
        for (int j = k >> 1; j > 0; j >>= 1) {
            for (int t = threadIdx.x; t < CHUNK / 2; t += 256) {
                int i = ((t & ~(j - 1)) << 1) | (t & (j - 1));
                int ixj = i + j;
                bool up = (((lbase + i) & k) == 0);
                unsigned long long A = s[i], Bv = s[ixj];
                if ((A > Bv) == up) { s[i] = Bv; s[ixj] = A; }
            }
            __syncthreads();
        }
    }
    for (int i = threadIdx.x; i < CHUNK; i += 256) g_keys[base + i] = s[i];
}

__global__ void k_gmerge(int j, int k) {
    int t = blockIdx.x * 256 + threadIdx.x;
    int b = t >> 14, tl = t & 16383;
    int i = ((tl & ~(j - 1)) << 1) | (tl & (j - 1));
    bool up = ((i & k) == 0);
    size_t gi = (size_t)b * NSORT + i;
    unsigned long long A = g_keys[gi], Bv = g_keys[gi + j];
    if ((A > Bv) == up) { g_keys[gi] = Bv; g_keys[gi + j] = A; }
}

__global__ void k_lmerge(int k) {
    __shared__ unsigned long long s[CHUNK];
    int base = blockIdx.x * CHUNK;
    int lbase = base & (NSORT - 1);
    for (int i = threadIdx.x; i < CHUNK; i += 256) s[i] = g_keys[base + i];
    __syncthreads();
    for (int j = CHUNK >> 1; j > 0; j >>= 1) {
        for (int t = threadIdx.x; t < CHUNK / 2; t += 256) {
            int i = ((t & ~(j - 1)) << 1) | (t & (j - 1));
            int ixj = i + j;
            bool up = (((lbase + i) & k) == 0);
            unsigned long long A = s[i], Bv = s[ixj];
            if ((A > Bv) == up) { s[i] = Bv; s[ixj] = A; }
        }
        __syncthreads();
    }
    for (int i = threadIdx.x; i < CHUNK; i += 256) g_keys[base + i] = s[i];
}

// ------------------------- 3. gather coords --------------------------------
__global__ void k_coords(const float* __restrict__ rc, const float* __restrict__ rf,
                         float* __restrict__ oc) {
    int t = blockIdx.x * 256 + threadIdx.x;
    int b = t >> 13, p = t & (PTR - 1);
    float y, x;
    if (p < NUNC) {
        unsigned idx = (unsigned)(g_keys[(size_t)b * NSORT + p] & 0xffffffffu);
        y = rc[((size_t)b * POS + idx) * 2 + 0];
        x = rc[((size_t)b * POS + idx) * 2 + 1];
    } else {
        int q = p - NUNC;
        y = rf[((size_t)b * NRAND + q) * 2 + 0];
        x = rf[((size_t)b * NRAND + q) * 2 + 1];
    }
    oc[(size_t)t * 2 + 0] = y;
    oc[(size_t)t * 2 + 1] = x;
}

// ------------------------- 4. feature sampling -> bf16 hi/lo ----------------
__global__ void k_sample(const float* __restrict__ coarse, const float* __restrict__ fine,
                         const float* __restrict__ oc) {
    int gt = blockIdx.x * 256 + threadIdx.x;
    int w = gt >> 5, lane = gt & 31;
    int b = w >> 13;
    float cy = oc[(size_t)w * 2 + 0], cx = oc[(size_t)w * 2 + 1];
    size_t row = (size_t)w * KP2;

    {   // fine -> cols [0..255] of Xa
        float y = cy * 256.f - 0.5f, x = cx * 256.f - 0.5f;
        float y0f = floorf(y), x0f = floorf(x);
        float wy = y - y0f, wx = x - x0f;
        int y0 = min(max((int)y0f, 0), FIH - 1);
        int y1 = min(max((int)y0f + 1, 0), FIH - 1);
        int x0 = min(max((int)x0f, 0), FIW - 1);
        int x1 = min(max((int)x0f + 1, 0), FIW - 1);
        const float* fb = fine + (size_t)b * FIH * FIW * FIC;
        const float4* f00 = (const float4*)(fb + ((size_t)y0 * FIW + x0) * FIC);
        const float4* f01 = (const float4*)(fb + ((size_t)y0 * FIW + x1) * FIC);
        const float4* f10 = (const float4*)(fb + ((size_t)y1 * FIW + x0) * FIC);
        const float4* f11 = (const float4*)(fb + ((size_t)y1 * FIW + x1) * FIC);
#pragma unroll
        for (int q = 0; q < 2; q++) {
            int c4 = lane + 32 * q;
            float4 a = f00[c4], b2 = f01[c4], c = f10[c4], d = f11[c4];
            float r0 = (1.f - wy) * ((1.f - wx) * a.x + wx * b2.x) + wy * ((1.f - wx) * c.x + wx * d.x);
            float r1 = (1.f - wy) * ((1.f - wx) * a.y + wx * b2.y) + wy * ((1.f - wx) * c.y + wx * d.y);
            float r2 = (1.f - wy) * ((1.f - wx) * a.z + wx * b2.z) + wy * ((1.f - wx) * c.z + wx * d.z);
            float r3 = (1.f - wy) * ((1.f - wx) * a.w + wx * b2.w) + wy * ((1.f - wx) * c.w + wx * d.w);
            uint2 hv, lv;
            hv.x = packbf(r0, r1); hv.y = packbf(r2, r3);
            lv.x = packbf(r0 - bf_hi(r0), r1 - bf_hi(r1));
            lv.y = packbf(r2 - bf_hi(r2), r3 - bf_hi(r3));
            *(uint2*)&g_Xa_hi[row + (size_t)c4 * 4] = hv;
            *(uint2*)&g_Xa_lo[row + (size_t)c4 * 4] = lv;
        }
    }
    {   // coarse residual -> cols [256..319] of Xa AND Xb (zeros past 274)
        float y = cy * 128.f - 0.5f, x = cx * 128.f - 0.5f;
        float y0f = floorf(y), x0f = floorf(x);
        float wy = y - y0f, wx = x - x0f;
        int y0 = min(max((int)y0f, 0), COH - 1);
        int y1 = min(max((int)y0f + 1, 0), COH - 1);
        int x0 = min(max((int)x0f, 0), COW - 1);
        int x1 = min(max((int)x0f + 1, 0), COW - 1);
        const float* cb = coarse + (size_t)b * COH * COW * CLS;
        float v[2];
#pragma unroll
        for (int j = 0; j < 2; j++) {
            int c = lane * 2 + j;
            if (c < CLS) {
                float a = cb[(y0 * COW + x0) * CLS + c];
                float b2 = cb[(y0 * COW + x1) * CLS + c];
                float cc = cb[(y1 * COW + x0) * CLS + c];
                float d = cb[(y1 * COW + x1) * CLS + c];
                v[j] = (1.f - wy) * ((1.f - wx) * a + wx * b2) +
                       wy * ((1.f - wx) * cc + wx * d);
            } else v[j] = 0.f;
        }
        uint32_t hv = packbf(v[0], v[1]);
        uint32_t lv = packbf(v[0] - bf_hi(v[0]), v[1] - bf_hi(v[1]));
        size_t off = row + 256 + (size_t)lane * 2;
        *(uint32_t*)&g_Xa_hi[off] = hv; *(uint32_t*)&g_Xa_lo[off] = lv;
        *(uint32_t*)&g_Xb_hi[off] = hv; *(uint32_t*)&g_Xb_lo[off] = lv;
    }
}

// ------------------------- 4b. prep W^T hi/lo ------------------------------
__global__ void k_prep_w(const float* __restrict__ w0, const float* __restrict__ w1,
                         const float* __restrict__ w2) {
    int t = blockIdx.x * 256 + threadIdx.x;   // 3*256*320
    if (t >= 3 * 256 * KP2) return;
    int l = t / (256 * KP2);
    int rem = t - l * 256 * KP2;
    int n = rem / KP2, k = rem - n * KP2;
    const float* W = (l == 0) ? w0 : ((l == 1) ? w1 : w2);
    int r;
    if (l == 0) r = (k < 256) ? (k + CLS) : ((k < KDIM) ? (k - 256) : -1);
    else        r = (k < KDIM) ? k : -1;
    float v = (r >= 0) ? W[(size_t)r * NH + n] : 0.f;
    float h = bf_hi(v);
    g_Wt_hi[t] = __float2bfloat16(v);
    g_Wt_lo[t] = __float2bfloat16(v - h);
}

// ------------------------- 5. HMMA GEMM (bf16 hi/lo split) -----------------
// Y[m,0..255] = relu(X[m,0..319] @ Wt^T + bias). CTA: M128 x N128, K chunks
// of 32, 2-stage cp.async pipeline. Warp tile 64x32 (2x4 warp grid).
#define PADK 40                      // smem row stride in bf16 (80 B)
#define ABYTES (128 * PADK * 2)      // 10240
#define BUFB   (4 * ABYTES)          // hi/lo x A/B per stage = 40960
#define SM_DYN (2 * BUFB)            // 81920

__global__ __launch_bounds__(256) void k_gemm_mma(
    const __nv_bfloat16* __restrict__ Xhi, const __nv_bfloat16* __restrict__ Xlo,
    const __nv_bfloat16* __restrict__ Whi, const __nv_bfloat16* __restrict__ Wlo,
    const float* __restrict__ bias,
    __nv_bfloat16* __restrict__ Yhi, __nv_bfloat16* __restrict__ Ylo) {
    extern __shared__ char smem[];
    __shared__ float sbias[128];
    uint32_t sb = smem_u32(smem);
    int tid = threadIdx.x, wid = tid >> 5, lane = tid & 31;
    int wm = wid & 1, wn = wid >> 1;           // warp grid 2 (M) x 4 (N)
    int m0 = (blockIdx.x >> 1) * 128;
    int n0 = (blockIdx.x & 1) * 128;

    if (tid < 128) sbias[tid] = bias[n0 + tid];

    float acc[4][4][4];
#pragma unroll
    for (int i = 0; i < 4; i++)
#pragma unroll
        for (int j = 0; j < 4; j++)
#pragma unroll
            for (int q = 0; q < 4; q++) acc[i][j][q] = 0.f;

    int lrow = tid >> 2;          // 0..63 : two rows per... (see below)
    int lq = tid & 3;             // 16B chunk within 64B row

    auto issue = [&](int c, int buf) {
        int kb = c * 32;
        uint32_t s0 = sb + buf * BUFB;
#pragma unroll
        for (int r = 0; r < 2; r++) {
            int row = lrow + r * 64;
            size_t gA = (size_t)(m0 + row) * KP2 + kb + lq * 8;
            size_t gB = (size_t)(n0 + row) * KP2 + kb + lq * 8;
            uint32_t soff = row * (PADK * 2) + lq * 16;
            cp16(s0 + soff, Xhi + gA);
            cp16(s0 + ABYTES + soff, Xlo + gA);
            cp16(s0 + 2 * ABYTES + soff, Whi + gB);
            cp16(s0 + 3 * ABYTES + soff, Wlo + gB);
        }
        cp_commit();
    };

    issue(0, 0);

    for (int c = 0; c < 10; c++) {
        if (c < 9) { issue(c + 1, (c + 1) & 1); cp_wait<1>(); }
        else cp_wait<0>();
        __syncthreads();
        uint32_t s0 = sb + (c & 1) * BUFB;
#pragma unroll
        for (int k16 = 0; k16 < 2; k16++) {
            uint32_t ah[4][4], al[4][4], bh[4][2], bl[4][2];
            int ka = k16 * 32 + ((lane >> 4) << 4);    // byte offset of k-half
            int kb2 = k16 * 32 + (((lane >> 3) & 1) << 4);
#pragma unroll
            for (int mt = 0; mt < 4; mt++) {
                int row = wm * 64 + mt * 16 + (lane & 15);
                uint32_t a = s0 + row * (PADK * 2) + ka;
                ldsm4(ah[mt], a);
                ldsm4(al[mt], a + ABYTES);
            }
#pragma unroll
            for (int nt = 0; nt < 4; nt++) {
                int n = wn * 32 + nt * 8 + (lane & 7);
                uint32_t a = s0 + 2 * ABYTES + n * (PADK * 2) + kb2;
                ldsm2(bh[nt], a);
                ldsm2(bl[nt], a + ABYTES);
            }
#pragma unroll
            for (int mt = 0; mt < 4; mt++)
#pragma unroll
                for (int nt = 0; nt < 4; nt++) {
                    mma_bf16(acc[mt][nt], ah[mt], bh[nt]);
                    mma_bf16(acc[mt][nt], ah[mt], bl[nt]);
                    mma_bf16(acc[mt][nt], al[mt], bh[nt]);
                }
        }
        __syncthreads();
    }

    // epilogue: bias + relu + hi/lo bf16 repack
#pragma unroll
    for (int mt = 0; mt < 4; mt++) {
#pragma unroll
        for (int nt = 0; nt < 4; nt++) {
            int gn = n0 + wn * 32 + nt * 8 + (lane & 3) * 2;
            float bi0 = sbias[gn - n0], bi1 = sbias[gn - n0 + 1];
#pragma unroll
            for (int h = 0; h < 2; h++) {
                int m = m0 + wm * 64 + mt * 16 + (lane >> 2) + h * 8;
                float v0 = acc[mt][nt][2 * h] + bi0;
                float v1 = acc[mt][nt][2 * h + 1] + bi1;
                v0 = v0 > 0.f ? v0 : 0.f;
                v1 = v1 > 0.f ? v1 : 0.f;
                *(uint32_t*)&Yhi[(size_t)m * KP2 + gn] = packbf(v0, v1);
                *(uint32_t*)&Ylo[(size_t)m * KP2 + gn] =
                    packbf(v0 - bf_hi(v0), v1 - bf_hi(v1));
            }
        }
    }
}

// ------------------------- 6. final layer (N=19) ---------------------------
__global__ __launch_bounds__(256) void k_final(const __nv_bfloat16* __restrict__ Xhi,
                                               const __nv_bfloat16* __restrict__ Xlo,
                                               const float* __restrict__ wf,
                                               const float* __restrict__ bf,
                                               float* __restrict__ out) {
    __shared__ float swf[KDIM * CLS];
    for (int i = threadIdx.x; i < KDIM * CLS; i += 256) swf[i] = wf[i];
    __syncthreads();
    int w = (blockIdx.x * 256 + threadIdx.x) >> 5;
    int lane = threadIdx.x & 31;
    const __nv_bfloat16* xh = Xhi + (size_t)w * KP2;
    const __nv_bfloat16* xl = Xlo + (size_t)w * KP2;
    float acc[CLS];
#pragma unroll
    for (int c = 0; c < CLS; c++) acc[c] = 0.f;
    for (int k = lane; k < KDIM; k += 32) {
        float xv = __bfloat162float(xh[k]) + __bfloat162float(xl[k]);
        const float* wr = &swf[k * CLS];
#pragma unroll
        for (int c = 0; c < CLS; c++) acc[c] += xv * wr[c];
    }
#pragma unroll
    for (int off = 16; off; off >>= 1)
#pragma unroll
        for (int c = 0; c < CLS; c++) acc[c] += __shfl_xor_sync(0xffffffffu, acc[c], off);
    if (lane == 0) {
        float* o = out + (size_t)w * CLS;
#pragma unroll
        for (int c = 0; c < CLS; c++) o[c] = acc[c] + bf[c];
    }
}

// ------------------------- 7. resize + softmax -----------------------------
__global__ void k_resize_softmax(const float* __restrict__ coarse, float* __restrict__ op) {
    int t = blockIdx.x * 256 + threadIdx.x;
    int b = t >> 18;
    int rem = t & 262143;
    int y = rem >> 9;
    int x = rem & 511;
    float sy = (y + 0.5f) * 0.25f - 0.5f;
    float sx = (x + 0.5f) * 0.25f - 0.5f;
    float y0f = floorf(sy), x0f = floorf(sx);
    float wy = sy - y0f, wx = sx - x0f;
    int y0 = min(max((int)y0f, 0), COH - 1);
    int y1 = min(max((int)y0f + 1, 0), COH - 1);
    int x0 = min(max((int)x0f, 0), COW - 1);
    int x1 = min(max((int)x0f + 1, 0), COW - 1);
    const float* cb = coarse + (size_t)b * COH * COW * CLS;
    const float* p00 = cb + (y0 * COW + x0) * CLS;
    const float* p01 = cb + (y0 * COW + x1) * CLS;
    const float* p10 = cb + (y1 * COW + x0) * CLS;
    const float* p11 = cb + (y1 * COW + x1) * CLS;
    float v[CLS];
    float m = -3.0e38f;
#pragma unroll
    for (int c = 0; c < CLS; c++) {
        float top = (1.f - wx) * p00[c] + wx * p01[c];
        float bot = (1.f - wx) * p10[c] + wx * p11[c];
        v[c] = (1.f - wy) * top + wy * bot;
        m = fmaxf(m, v[c]);
    }
    float s = 0.f;
#pragma unroll
    for (int c = 0; c < CLS; c++) {
        v[c] = expf(v[c] - m);
        s += v[c];
    }
    float inv = 1.f / s;
    float* o = op + (size_t)t * CLS;
#pragma unroll
    for (int c = 0; c < CLS; c++) o[c] = v[c] * inv;
}

// ------------------------- launch ------------------------------------------
extern "C" void kernel_launch(void* const* d_in, const int* in_sizes, int n_in, void* d_out,
                              int out_size) {
    const float* coarse = (const float*)d_in[1];
    const float* fine0 = (const float*)d_in[2];
    const float* rand_coords = (const float*)d_in[3];
    const float* rand_fill = (const float*)d_in[4];
    const float* w0 = (const float*)d_in[5];
    const float* b0 = (const float*)d_in[6];
    const float* w1 = (const float*)d_in[7];
    const float* b1 = (const float*)d_in[8];
    const float* w2 = (const float*)d_in[9];
    const float* b2 = (const float*)d_in[10];
    const float* wf = (const float*)d_in[11];
    const float* bf = (const float*)d_in[12];
    float* out = (float*)d_out;

    const size_t PROBS = (size_t)Bn * 512 * 512 * CLS;
    const size_t LOGITS = (size_t)Bn * PTR * CLS;
    float* out_probs = out;
    float* out_logits = out + PROBS;
    float* out_coords = out + PROBS + LOGITS;

    void *pXah, *pXal, *pXbh, *pXbl, *pWh, *pWl;
    cudaGetSymbolAddress(&pXah, g_Xa_hi);
    cudaGetSymbolAddress(&pXal, g_Xa_lo);
    cudaGetSymbolAddress(&pXbh, g_Xb_hi);
    cudaGetSymbolAddress(&pXbl, g_Xb_lo);
    cudaGetSymbolAddress(&pWh, g_Wt_hi);
    cudaGetSymbolAddress(&pWl, g_Wt_lo);
    __nv_bfloat16* Xah = (__nv_bfloat16*)pXah;
    __nv_bfloat16* Xal = (__nv_bfloat16*)pXal;
    __nv_bfloat16* Xbh = (__nv_bfloat16*)pXbh;
    __nv_bfloat16* Xbl = (__nv_bfloat16*)pXbl;
    __nv_bfloat16* Wh = (__nv_bfloat16*)pWh;
    __nv_bfloat16* Wl = (__nv_bfloat16*)pWl;

    cudaFuncSetAttribute(k_gemm_mma, cudaFuncAttributeMaxDynamicSharedMemorySize, SM_DYN);

    // independent big-memory path + weight prep first
    k_resize_softmax<<<4096, 256>>>(coarse, out_probs);
    k_prep_w<<<960, 256>>>(w0, w1, w2);

    // uncertainty + per-batch bitonic sort of 32768 keys
    k_uncertainty<<<512, 256>>>(coarse, rand_coords);
    k_lsort<<<32, 256>>>();
    k_gmerge<<<256, 256>>>(4096, 8192);
    k_lmerge<<<32, 256>>>(8192);
    k_gmerge<<<256, 256>>>(8192, 16384);
    k_gmerge<<<256, 256>>>(4096, 16384);
    k_lmerge<<<32, 256>>>(16384);
    k_gmerge<<<256, 256>>>(16384, 32768);
    k_gmerge<<<256, 256>>>(8192, 32768);
    k_gmerge<<<256, 256>>>(4096, 32768);
    k_lmerge<<<32, 256>>>(32768);

    k_coords<<<128, 256>>>(rand_coords, rand_fill, out_coords);
    k_sample<<<4096, 256>>>(coarse, fine0, out_coords);

    const int WSTR = 256 * KP2;
    k_gemm_mma<<<512, 256, SM_DYN>>>(Xah, Xal, Wh, Wl, b0, Xbh, Xbl);
    k_gemm_mma<<<512, 256, SM_DYN>>>(Xbh, Xbl, Wh + WSTR, Wl + WSTR, b1, Xah, Xal);
    k_gemm_mma<<<512, 256, SM_DYN>>>(Xah, Xal, Wh + 2 * WSTR, Wl + 2 * WSTR, b2, Xbh, Xbl);
    k_final<<<4096, 256>>>(Xbh, Xbl, wf, bf, out_logits);
}

// round 5
// speedup vs baseline: 1.6754x; 1.0516x over previous
#include <cuda_runtime.h>
#include <cuda_bf16.h>
#include <math.h>
#include <stdint.h>

#define Bn    4
#define COH   128
#define COW   128
#define CLS   19
#define FIH   256
#define FIW   256
#define FIC   256
#define PTR   8192
#define POS   24576
#define NUNC  6144
#define NRAND 2048
#define NSORT 32768
#define KDIM  275
#define NH    256
#define CHUNK 4096
#define KP2   288        // padded K for tensor path (9 x 32)
#define NC    9          // K chunks
#define MTOT  32768      // Bn*PTR

// ------------------------- scratch (device globals, no allocs) -------------
__device__ unsigned long long g_keys[Bn * NSORT];
__device__ __align__(16) __nv_bfloat16 g_Xa_hi[(size_t)MTOT * KP2];
__device__ __align__(16) __nv_bfloat16 g_Xa_lo[(size_t)MTOT * KP2];
__device__ __align__(16) __nv_bfloat16 g_Xb_hi[(size_t)MTOT * KP2];
__device__ __align__(16) __nv_bfloat16 g_Xb_lo[(size_t)MTOT * KP2];
__device__ __align__(16) __nv_bfloat16 g_Wt_hi[3 * 256 * KP2];
__device__ __align__(16) __nv_bfloat16 g_Wt_lo[3 * 256 * KP2];

// ------------------------- small helpers -----------------------------------
__device__ __forceinline__ float lerp_rn(float w, float a, float b) {
    return __fadd_rn(__fmul_rn(__fsub_rn(1.0f, w), a), __fmul_rn(w, b));
}
__device__ __forceinline__ float bf_hi(float v) {
    return __bfloat162float(__float2bfloat16(v));
}
__device__ __forceinline__ uint32_t packbf(float e0, float e1) {
    uint32_t r;
    asm("cvt.rn.bf16x2.f32 %0, %1, %2;" : "=r"(r) : "f"(e1), "f"(e0));
    return r;
}
__device__ __forceinline__ uint32_t smem_u32(const void* p) {
    uint32_t a;
    asm("{ .reg .u64 t; cvta.to.shared.u64 t, %1; cvt.u32.u64 %0, t; }" : "=r"(a) : "l"(p));
    return a;
}
__device__ __forceinline__ void cp16(uint32_t dst, const void* src) {
    asm volatile("cp.async.cg.shared.global [%0], [%1], 16;" :: "r"(dst), "l"(src) : "memory");
}
__device__ __forceinline__ void cp_commit() {
    asm volatile("cp.async.commit_group;" ::: "memory");
}
template <int N>
__device__ __forceinline__ void cp_wait() {
    asm volatile("cp.async.wait_group %0;" :: "n"(N) : "memory");
}
__device__ __forceinline__ void ldsm4(uint32_t r[4], uint32_t addr) {
    asm volatile("ldmatrix.sync.aligned.m8n8.x4.shared.b16 {%0,%1,%2,%3}, [%4];"
                 : "=r"(r[0]), "=r"(r[1]), "=r"(r[2]), "=r"(r[3]) : "r"(addr));
}
__device__ __forceinline__ void ldsm2(uint32_t r[2], uint32_t addr) {
    asm volatile("ldmatrix.sync.aligned.m8n8.x2.shared.b16 {%0,%1}, [%2];"
                 : "=r"(r[0]), "=r"(r[1]) : "r"(addr));
}
__device__ __forceinline__ void mma_bf16(float c[4], const uint32_t a[4], const uint32_t b[2]) {
    asm volatile(
        "mma.sync.aligned.m16n8k16.row.col.f32.bf16.bf16.f32 "
        "{%0,%1,%2,%3}, {%4,%5,%6,%7}, {%8,%9}, {%0,%1,%2,%3};"
        : "+f"(c[0]), "+f"(c[1]), "+f"(c[2]), "+f"(c[3])
        : "r"(a[0]), "r"(a[1]), "r"(a[2]), "r"(a[3]), "r"(b[0]), "r"(b[1]));
}

// ------------------------- 1. uncertainty (bit-exact path) ------------------
__global__ void k_uncertainty(const float* __restrict__ coarse, const float* __restrict__ rc) {
    int t = blockIdx.x * 256 + threadIdx.x;
    int b = t >> 15;
    int p = t & (NSORT - 1);
    if (p >= POS) { g_keys[t] = ~0ull; return; }
    float cy = rc[((size_t)b * POS + p) * 2 + 0];
    float cx = rc[((size_t)b * POS + p) * 2 + 1];
    float y = __fadd_rn(__fmul_rn(cy, 128.f), -0.5f);
    float x = __fadd_rn(__fmul_rn(cx, 128.f), -0.5f);
    float y0f = floorf(y), x0f = floorf(x);
    float wy = __fsub_rn(y, y0f);
    float wx = __fsub_rn(x, x0f);
    int y0 = min(max((int)y0f, 0), COH - 1);
    int y1 = min(max((int)y0f + 1, 0), COH - 1);
    int x0 = min(max((int)x0f, 0), COW - 1);
    int x1 = min(max((int)x0f + 1, 0), COW - 1);
    const float* cb = coarse + (size_t)b * COH * COW * CLS;
    const float* p00 = cb + (y0 * COW + x0) * CLS;
    const float* p01 = cb + (y0 * COW + x1) * CLS;
    const float* p10 = cb + (y1 * COW + x0) * CLS;
    const float* p11 = cb + (y1 * COW + x1) * CLS;
    float m1 = -3.0e38f, m2 = -3.0e38f;
#pragma unroll
    for (int c = 0; c < CLS; c++) {
        float top = lerp_rn(wx, p00[c], p01[c]);
        float bot = lerp_rn(wx, p10[c], p11[c]);
        float v = lerp_rn(wy, top, bot);
        if (v > m1) { m2 = m1; m1 = v; }
        else if (v > m2) m2 = v;
    }
    float unc = __fsub_rn(m2, m1);
    unsigned u = __float_as_uint(unc);
    u = (u & 0x80000000u) ? ~u : (u | 0x80000000u);
    u = ~u;
    g_keys[t] = ((unsigned long long)u << 32) | (unsigned)p;
}

// ------------------------- 2. bitonic sort (1024-thread blocks) -------------
__global__ __launch_bounds__(1024) void k_lsort() {
    __shared__ unsigned long long s[CHUNK];
    int base = blockIdx.x * CHUNK;
    int lbase = base & (NSORT - 1);
    for (int i = threadIdx.x; i < CHUNK; i += 1024) s[i] = g_keys[base + i];
    __syncthreads();
    for (int k = 2; k <= CHUNK; k <<= 1) {
        for (int j = k >> 1; j > 0; j >>= 1) {
#pragma unroll
            for (int r = 0; r < 2; r++) {
                int t = threadIdx.x + r * 1024;
                int i = ((t & ~(j - 1)) << 1) | (t & (j - 1));
                int ixj = i + j;
                bool up = (((lbase + i) & k) == 0);
                unsigned long long A = s[i], Bv = s[ixj];
                if ((A > Bv) == up) { s[i] = Bv; s[ixj] = A; }
            }
            __syncthreads();
        }
    }
    for (int i = threadIdx.x; i < CHUNK; i += 1024) g_keys[base + i] = s[i];
}

__global__ void k_gmerge(int j, int k) {
    int t = blockIdx.x * 256 + threadIdx.x;
    int b = t >> 14, tl = t & 16383;
    int i = ((tl & ~(j - 1)) << 1) | (tl & (j - 1));
    bool up = ((i & k) == 0);
    size_t gi = (size_t)b * NSORT + i;
    unsigned long long A = g_keys[gi], Bv = g_keys[gi + j];
    if ((A > Bv) == up) { g_keys[gi] = Bv; g_keys[gi + j] = A; }
}

__device__ __forceinline__ void lmerge_body(int base, int lbase, int k) {
    __shared__ unsigned long long s[CHUNK];
    for (int i = threadIdx.x; i < CHUNK; i += 1024) s[i] = g_keys[base + i];
    __syncthreads();
    for (int j = CHUNK >> 1; j > 0; j >>= 1) {
#pragma unroll
        for (int r = 0; r < 2; r++) {
            int t = threadIdx.x + r * 1024;
            int i = ((t & ~(j - 1)) << 1) | (t & (j - 1));
            int ixj = i + j;
            bool up = (((lbase + i) & k) == 0);
            unsigned long long A = s[i], Bv = s[ixj];
            if ((A > Bv) == up) { s[i] = Bv; s[ixj] = A; }
        }
        __syncthreads();
    }
    for (int i = threadIdx.x; i < CHUNK; i += 1024) g_keys[base + i] = s[i];
}

__global__ __launch_bounds__(1024) void k_lmerge(int k) {
    int base = blockIdx.x * CHUNK;
    lmerge_body(base, base & (NSORT - 1), k);
}

// final merge: only chunks 0,1 of each batch carry the needed top-6144
__global__ __launch_bounds__(1024) void k_lmerge_top() {
    int b = blockIdx.x >> 1, c = blockIdx.x & 1;
    lmerge_body(b * NSORT + c * CHUNK, c * CHUNK, NSORT);
}

// ------------------------- 4. sampling + coords -> bf16 hi/lo ---------------
__global__ void k_sample(const float* __restrict__ coarse, const float* __restrict__ fine,
                         const float* __restrict__ rc, const float* __restrict__ rf,
                         float* __restrict__ oc) {
    int gt = blockIdx.x * 256 + threadIdx.x;
    int w = gt >> 5, lane = gt & 31;
    int b = w >> 13, p = w & (PTR - 1);
    float cy, cx;
    if (p < NUNC) {
        unsigned idx = (unsigned)(g_keys[(size_t)b * NSORT + p] & 0xffffffffu);
        cy = rc[((size_t)b * POS + idx) * 2 + 0];
        cx = rc[((size_t)b * POS + idx) * 2 + 1];
    } else {
        int q = p - NUNC;
        cy = rf[((size_t)b * NRAND + q) * 2 + 0];
        cx = rf[((size_t)b * NRAND + q) * 2 + 1];
    }
    if (lane == 0) {
        oc[(size_t)w * 2 + 0] = cy;
        oc[(size_t)w * 2 + 1] = cx;
    }
    size_t row = (size_t)w * KP2;

    {   // fine -> cols [0..255] of Xa
        float y = cy * 256.f - 0.5f, x = cx * 256.f - 0.5f;
        float y0f = floorf(y), x0f = floorf(x);
        float wy = y - y0f, wx = x - x0f;
        int y0 = min(max((int)y0f, 0), FIH - 1);
        int y1 = min(max((int)y0f + 1, 0), FIH - 1);
        int x0 = min(max((int)x0f, 0), FIW - 1);
        int x1 = min(max((int)x0f + 1, 0), FIW - 1);
        const float* fb = fine + (size_t)b * FIH * FIW * FIC;
        const float4* f00 = (const float4*)(fb + ((size_t)y0 * FIW + x0) * FIC);
        const float4* f01 = (const float4*)(fb + ((size_t)y0 * FIW + x1) * FIC);
        const float4* f10 = (const float4*)(fb + ((size_t)y1 * FIW + x0) * FIC);
        const float4* f11 = (const float4*)(fb + ((size_t)y1 * FIW + x1) * FIC);
#pragma unroll
        for (int q = 0; q < 2; q++) {
            int c4 = lane + 32 * q;
            float4 a = f00[c4], b2 = f01[c4], c = f10[c4], d = f11[c4];
            float r0 = (1.f - wy) * ((1.f - wx) * a.x + wx * b2.x) + wy * ((1.f - wx) * c.x + wx * d.x);
            float r1 = (1.f - wy) * ((1.f - wx) * a.y + wx * b2.y) + wy * ((1.f - wx) * c.y + wx * d.y);
            float r2 = (1.f - wy) * ((1.f - wx) * a.z + wx * b2.z) + wy * ((1.f - wx) * c.z + wx * d.z);
            float r3 = (1.f - wy) * ((1.f - wx) * a.w + wx * b2.w) + wy * ((1.f - wx) * c.w + wx * d.w);
            uint2 hv, lv;
            hv.x = packbf(r0, r1); hv.y = packbf(r2, r3);
            lv.x = packbf(r0 - bf_hi(r0), r1 - bf_hi(r1));
            lv.y = packbf(r2 - bf_hi(r2), r3 - bf_hi(r3));
            *(uint2*)&g_Xa_hi[row + (size_t)c4 * 4] = hv;
            *(uint2*)&g_Xa_lo[row + (size_t)c4 * 4] = lv;
        }
    }
    {   // coarse residual -> cols [256..287] of Xa AND Xb (zeros past 274)
        float y = cy * 128.f - 0.5f, x = cx * 128.f - 0.5f;
        float y0f = floorf(y), x0f = floorf(x);
        float wy = y - y0f, wx = x - x0f;
        int y0 = min(max((int)y0f, 0), COH - 1);
        int y1 = min(max((int)y0f + 1, 0), COH - 1);
        int x0 = min(max((int)x0f, 0), COW - 1);
        int x1 = min(max((int)x0f + 1, 0), COW - 1);
        const float* cb = coarse + (size_t)b * COH * COW * CLS;
        int c = lane;
        float v = 0.f;
        if (c < CLS) {
            float a = cb[(y0 * COW + x0) * CLS + c];
            float b2 = cb[(y0 * COW + x1) * CLS + c];
            float cc = cb[(y1 * COW + x0) * CLS + c];
            float d = cb[(y1 * COW + x1) * CLS + c];
            v = (1.f - wy) * ((1.f - wx) * a + wx * b2) + wy * ((1.f - wx) * cc + wx * d);
        }
        __nv_bfloat16 hv = __float2bfloat16(v);
        __nv_bfloat16 lv = __float2bfloat16(v - bf_hi(v));
        size_t off = row + 256 + lane;
        g_Xa_hi[off] = hv; g_Xa_lo[off] = lv;
        g_Xb_hi[off] = hv; g_Xb_lo[off] = lv;
    }
}

// ------------------------- 4b. prep W^T hi/lo ------------------------------
__global__ void k_prep_w(const float* __restrict__ w0, const float* __restrict__ w1,
                         const float* __restrict__ w2) {
    int t = blockIdx.x * 256 + threadIdx.x;   // 3*256*288
    if (t >= 3 * 256 * KP2) return;
    int l = t / (256 * KP2);
    int rem = t - l * 256 * KP2;
    int n = rem / KP2, k = rem - n * KP2;
    const float* W = (l == 0) ? w0 : ((l == 1) ? w1 : w2);
    int r;
    if (l == 0) r = (k < 256) ? (k + CLS) : ((k < KDIM) ? (k - 256) : -1);
    else        r = (k < KDIM) ? k : -1;
    float v = (r >= 0) ? W[(size_t)r * NH + n] : 0.f;
    float h = bf_hi(v);
    g_Wt_hi[t] = __float2bfloat16(v);
    g_Wt_lo[t] = __float2bfloat16(v - h);
}

// ------------------------- 5. HMMA GEMM (bf16 hi/lo split) -----------------
#define PADK 40                      // smem row stride in bf16 (80 B)
#define ABYTES (128 * PADK * 2)      // 10240
#define BUFB   (4 * ABYTES)          // hi/lo x A/B per stage = 40960
#define SM_DYN (3 * BUFB)            // 122880 (3-stage pipeline)
#define RSTR   272                   // epilogue staging row stride (bytes)

__global__ __launch_bounds__(256) void k_gemm_mma(
    const __nv_bfloat16* __restrict__ Xhi, const __nv_bfloat16* __restrict__ Xlo,
    const __nv_bfloat16* __restrict__ Whi, const __nv_bfloat16* __restrict__ Wlo,
    const float* __restrict__ bias,
    __nv_bfloat16* __restrict__ Yhi, __nv_bfloat16* __restrict__ Ylo) {
    extern __shared__ char smem[];
    __shared__ float sbias[128];
    uint32_t sb = smem_u32(smem);
    int tid = threadIdx.x, wid = tid >> 5, lane = tid & 31;
    int wm = wid & 1, wn = wid >> 1;           // warp grid 2 (M) x 4 (N)
    int m0 = (blockIdx.x >> 1) * 128;
    int n0 = (blockIdx.x & 1) * 128;

    if (tid < 128) sbias[tid] = bias[n0 + tid];

    float acc[4][4][4];
#pragma unroll
    for (int i = 0; i < 4; i++)
#pragma unroll
        for (int j = 0; j < 4; j++)
#pragma unroll
            for (int q = 0; q < 4; q++) acc[i][j][q] = 0.f;

    int lrow = tid >> 2;
    int lq = tid & 3;

    auto issue = [&](int c, int buf) {
        int kb = c * 32;
        uint32_t s0 = sb + buf * BUFB;
#pragma unroll
        for (int r = 0; r < 2; r++) {
            int row = lrow + r * 64;
            size_t gA = (size_t)(m0 + row) * KP2 + kb + lq * 8;
            size_t gB = (size_t)(n0 + row) * KP2 + kb + lq * 8;
            uint32_t soff = row * (PADK * 2) + lq * 16;
            cp16(s0 + soff, Xhi + gA);
            cp16(s0 + ABYTES + soff, Xlo + gA);
            cp16(s0 + 2 * ABYTES + soff, Whi + gB);
            cp16(s0 + 3 * ABYTES + soff, Wlo + gB);
        }
        cp_commit();
    };

    issue(0, 0);
    issue(1, 1);

    for (int c = 0; c < NC; c++) {
        if (c <= NC - 3) { issue(c + 2, (c + 2) % 3); cp_wait<2>(); }
        else if (c == NC - 2) cp_wait<1>();
        else cp_wait<0>();
        __syncthreads();
        uint32_t s0 = sb + (c % 3) * BUFB;
#pragma unroll
        for (int k16 = 0; k16 < 2; k16++) {
            uint32_t ah[4][4], al[4][4], bh[4][2], bl[4][2];
            int ka = k16 * 32 + ((lane >> 4) << 4);
            int kb2 = k16 * 32 + (((lane >> 3) & 1) << 4);
#pragma unroll
            for (int mt = 0; mt < 4; mt++) {
                int row = wm * 64 + mt * 16 + (lane & 15);
                uint32_t a = s0 + row * (PADK * 2) + ka;
                ldsm4(ah[mt], a);
                ldsm4(al[mt], a + ABYTES);
            }
#pragma unroll
            for (int nt = 0; nt < 4; nt++) {
                int n = wn * 32 + nt * 8 + (lane & 7);
                uint32_t a = s0 + 2 * ABYTES + n * (PADK * 2) + kb2;
                ldsm2(bh[nt], a);
                ldsm2(bl[nt], a + ABYTES);
            }
#pragma unroll
            for (int mt = 0; mt < 4; mt++)
#pragma unroll
                for (int nt = 0; nt < 4; nt++) {
                    mma_bf16(acc[mt][nt], ah[mt], bh[nt]);
                    mma_bf16(acc[mt][nt], ah[mt], bl[nt]);
                    mma_bf16(acc[mt][nt], al[mt], bh[nt]);
                }
        }
        __syncthreads();
    }

    // epilogue: bias + relu, stage in smem, coalesced uint4 stores (hi then lo)
#pragma unroll
    for (int pass = 0; pass < 2; pass++) {
        __syncthreads();
#pragma unroll
        for (int mt = 0; mt < 4; mt++)
#pragma unroll
            for (int nt = 0; nt < 4; nt++) {
                int col = wn * 32 + nt * 8 + (lane & 3) * 2;
                float bi0 = sbias[col], bi1 = sbias[col + 1];
#pragma unroll
                for (int h = 0; h < 2; h++) {
                    int row = wm * 64 + mt * 16 + (lane >> 2) + h * 8;
                    float v0 = acc[mt][nt][2 * h] + bi0;
                    float v1 = acc[mt][nt][2 * h + 1] + bi1;
                    v0 = v0 > 0.f ? v0 : 0.f;
                    v1 = v1 > 0.f ? v1 : 0.f;
                    uint32_t pv = (pass == 0)
                        ? packbf(v0, v1)
                        : packbf(v0 - bf_hi(v0), v1 - bf_hi(v1));
                    *(uint32_t*)(smem + row * RSTR + col * 2) = pv;
                }
            }
        __syncthreads();
        __nv_bfloat16* Y = (pass == 0) ? Yhi : Ylo;
#pragma unroll
        for (int i = 0; i < 8; i++) {
            int u = tid + i * 256;
            int row = u >> 4, q = u & 15;
            uint4 v = *(uint4*)(smem + row * RSTR + q * 16);
            *(uint4*)&Y[(size_t)(m0 + row) * KP2 + n0 + q * 8] = v;
        }
    }
}

// ------------------------- 6. final layer (N=19) ---------------------------
__global__ __launch_bounds__(256) void k_final(const __nv_bfloat16* __restrict__ Xhi,
                                               const __nv_bfloat16* __restrict__ Xlo,
                                               const float* __restrict__ wf,
                                               const float* __restrict__ bf,
                                               float* __restrict__ out) {
    __shared__ float swf[KDIM * CLS];
    for (int i = threadIdx.x; i < KDIM * CLS; i += 256) swf[i] = wf[i];
    __syncthreads();
    int w = (blockIdx.x * 256 + threadIdx.x) >> 5;
    int lane = threadIdx.x & 31;
    const __nv_bfloat16* xh = Xhi + (size_t)w * KP2;
    const __nv_bfloat16* xl = Xlo + (size_t)w * KP2;
    float acc[CLS];
#pragma unroll
    for (int c = 0; c < CLS; c++) acc[c] = 0.f;
    for (int k = lane; k < KDIM; k += 32) {
        float xv = __bfloat162float(xh[k]) + __bfloat162float(xl[k]);
        const float* wr = &swf[k * CLS];
#pragma unroll
        for (int c = 0; c < CLS; c++) acc[c] += xv * wr[c];
    }
#pragma unroll
    for (int off = 16; off; off >>= 1)
#pragma unroll
        for (int c = 0; c < CLS; c++) acc[c] += __shfl_xor_sync(0xffffffffu, acc[c], off);
    if (lane == 0) {
        float* o = out + (size_t)w * CLS;
#pragma unroll
        for (int c = 0; c < CLS; c++) o[c] = acc[c] + bf[c];
    }
}

// ------------------------- 7. resize + softmax -----------------------------
__global__ void k_resize_softmax(const float* __restrict__ coarse, float* __restrict__ op) {
    int t = blockIdx.x * 256 + threadIdx.x;
    int b = t >> 18;
    int rem = t & 262143;
    int y = rem >> 9;
    int x = rem & 511;
    float sy = (y + 0.5f) * 0.25f - 0.5f;
    float sx = (x + 0.5f) * 0.25f - 0.5f;
    float y0f = floorf(sy), x0f = floorf(sx);
    float wy = sy - y0f, wx = sx - x0f;
    int y0 = min(max((int)y0f, 0), COH - 1);
    int y1 = min(max((int)y0f + 1, 0), COH - 1);
    int x0 = min(max((int)x0f, 0), COW - 1);
    int x1 = min(max((int)x0f + 1, 0), COW - 1);
    const float* cb = coarse + (size_t)b * COH * COW * CLS;
    const float* p00 = cb + (y0 * COW + x0) * CLS;
    const float* p01 = cb + (y0 * COW + x1) * CLS;
    const float* p10 = cb + (y1 * COW + x0) * CLS;
    const float* p11 = cb + (y1 * COW + x1) * CLS;
    float v[CLS];
    float m = -3.0e38f;
#pragma unroll
    for (int c = 0; c < CLS; c++) {
        float top = (1.f - wx) * p00[c] + wx * p01[c];
        float bot = (1.f - wx) * p10[c] + wx * p11[c];
        v[c] = (1.f - wy) * top + wy * bot;
        m = fmaxf(m, v[c]);
    }
    float s = 0.f;
#pragma unroll
    for (int c = 0; c < CLS; c++) {
        v[c] = expf(v[c] - m);
        s += v[c];
    }
    float inv = 1.f / s;
    float* o = op + (size_t)t * CLS;
#pragma unroll
    for (int c = 0; c < CLS; c++) o[c] = v[c] * inv;
}

// ------------------------- launch ------------------------------------------
extern "C" void kernel_launch(void* const* d_in, const int* in_sizes, int n_in, void* d_out,
                              int out_size) {
    const float* coarse = (const float*)d_in[1];
    const float* fine0 = (const float*)d_in[2];
    const float* rand_coords = (const float*)d_in[3];
    const float* rand_fill = (const float*)d_in[4];
    const float* w0 = (const float*)d_in[5];
    const float* b0 = (const float*)d_in[6];
    const float* w1 = (const float*)d_in[7];
    const float* b1 = (const float*)d_in[8];
    const float* w2 = (const float*)d_in[9];
    const float* b2 = (const float*)d_in[10];
    const float* wf = (const float*)d_in[11];
    const float* bf = (const float*)d_in[12];
    float* out = (float*)d_out;

    const size_t PROBS = (size_t)Bn * 512 * 512 * CLS;
    const size_t LOGITS = (size_t)Bn * PTR * CLS;
    float* out_probs = out;
    float* out_logits = out + PROBS;
    float* out_coords = out + PROBS + LOGITS;

    void *pXah, *pXal, *pXbh, *pXbl, *pWh, *pWl;
    cudaGetSymbolAddress(&pXah, g_Xa_hi);
    cudaGetSymbolAddress(&pXal, g_Xa_lo);
    cudaGetSymbolAddress(&pXbh, g_Xb_hi);
    cudaGetSymbolAddress(&pXbl, g_Xb_lo);
    cudaGetSymbolAddress(&pWh, g_Wt_hi);
    cudaGetSymbolAddress(&pWl, g_Wt_lo);
    __nv_bfloat16* Xah = (__nv_bfloat16*)pXah;
    __nv_bfloat16* Xal = (__nv_bfloat16*)pXal;
    __nv_bfloat16* Xbh = (__nv_bfloat16*)pXbh;
    __nv_bfloat16* Xbl = (__nv_bfloat16*)pXbl;
    __nv_bfloat16* Wh = (__nv_bfloat16*)pWh;
    __nv_bfloat16* Wl = (__nv_bfloat16*)pWl;

    cudaFuncSetAttribute(k_gemm_mma, cudaFuncAttributeMaxDynamicSharedMemorySize, SM_DYN);

    // independent big-memory path + weight prep first
    k_resize_softmax<<<4096, 256>>>(coarse, out_probs);
    k_prep_w<<<864, 256>>>(w0, w1, w2);

    // uncertainty + per-batch bitonic sort of 32768 keys
    k_uncertainty<<<512, 256>>>(coarse, rand_coords);
    k_lsort<<<32, 1024>>>();
    k_gmerge<<<256, 256>>>(4096, 8192);
    k_lmerge<<<32, 1024>>>(8192);
    k_gmerge<<<256, 256>>>(8192, 16384);
    k_gmerge<<<256, 256>>>(4096, 16384);
    k_lmerge<<<32, 1024>>>(16384);
    k_gmerge<<<256, 256>>>(16384, 32768);
    k_gmerge<<<256, 256>>>(8192, 32768);
    k_gmerge<<<256, 256>>>(4096, 32768);
    k_lmerge_top<<<8, 1024>>>();

    k_sample<<<4096, 256>>>(coarse, fine0, rand_coords, rand_fill, out_coords);

    const int WSTR = 256 * KP2;
    k_gemm_mma<<<512, 256, SM_DYN>>>(Xah, Xal, Wh, Wl, b0, Xbh, Xbl);
    k_gemm_mma<<<512, 256, SM_DYN>>>(Xbh, Xbl, Wh + WSTR, Wl + WSTR, b1, Xah, Xal);
    k_gemm_mma<<<512, 256, SM_DYN>>>(Xah, Xal, Wh + 2 * WSTR, Wl + 2 * WSTR, b2, Xbh, Xbl);
    k_final<<<4096, 256>>>(Xbh, Xbl, wf, bf, out_logits);
}